// round 8
// baseline (speedup 1.0000x reference)
#include <cuda_runtime.h>
#include <cuda_bf16.h>
#include <cstdint>

// Fixed shapes
#define Nb 8
#define Ld 4096
#define Sd 4096
#define Hh 8
#define Dd 64
#define Mm 64
#define CH 16           // split-K chunks over S
#define SC (Sd / CH)    // 256 s-rows per chunk
#define TS 8            // phase-2 L segments (512 CTAs, 8 tiles each)
#define EPSV 1e-6f
#define NH (Nb * Hh)

// Scratch (allocation-free rule: __device__ globals)
__device__ float g_KVp[CH * NH * Dd * Mm];   // per-chunk partial KV (fp32)
__device__ float g_Ksp[CH * NH * Dd];        // per-chunk partial Ksum (fp32)
__device__ float g_KV[NH * Dd * Mm];         // reduced KV (tf32 bit patterns)
__device__ float g_Ksum[NH * Dd];            // reduced Ksum (fp32)

__device__ __forceinline__ float phi(float x) {
    return x > 0.f ? x + 1.f : __expf(x);    // elu(x)+1
}

__device__ __forceinline__ uint32_t to_tf32(float x) {
    uint32_t u;
    asm("cvt.rna.tf32.f32 %0, %1;" : "=r"(u) : "f"(x));
    return u;
}

__device__ __forceinline__ void mma_tf32(float* d,
                                         uint32_t a0, uint32_t a1, uint32_t a2, uint32_t a3,
                                         uint32_t b0, uint32_t b1) {
    asm volatile(
        "mma.sync.aligned.m16n8k8.row.col.f32.tf32.tf32.f32 "
        "{%0,%1,%2,%3}, {%4,%5,%6,%7}, {%8,%9}, {%0,%1,%2,%3};\n"
        : "+f"(d[0]), "+f"(d[1]), "+f"(d[2]), "+f"(d[3])
        : "r"(a0), "r"(a1), "r"(a2), "r"(a3), "r"(b0), "r"(b1));
}

// ───────────────────────── Phase 1: per-chunk KV partials ─────────────────────────
// grid (CH, H, N), 256 threads (8 warps). s-split warp tiling:
//   warp q = warp&3 owns output tile d0=(q>>1)*32, m0=(q&1)*32 (32x32)
//   warps 0-3 process s rows [0,16) of each tile, warps 4-7 rows [16,32);
//   cross-half acc reduction once at the end via smem.
__global__ __launch_bounds__(256) void la_kv_kernel(const float* __restrict__ kk,
                                                    const float* __restrict__ vv,
                                                    const float* __restrict__ mask) {
    const int c = blockIdx.x, h = blockIdx.y, n = blockIdx.z;
    const int nh = n * Hh + h;
    const int tid = threadIdx.x;
    const int warp = tid >> 5, lane = tid & 31;
    const int r = lane >> 2, q4 = lane & 3;
    const int wq = warp & 3;
    const int d0 = (wq >> 1) * 32, m0 = (wq & 1) * 32;
    const int sh = (warp >> 2) * 16;          // s-half offset
    const int lrow = tid >> 4, lcol = tid & 15;

    __shared__ float Ks[32][72];
    __shared__ float Vs[32][72];
    __shared__ float Red[4][32][32];          // upper-half acc deposit
    __shared__ float ksum_s[64];

    if (tid < 64) ksum_s[tid] = 0.f;

    float acc[2][4][4] = {};                  // [d-subtile 16][m-subtile 8][frag]
    float ks4[4] = {0.f, 0.f, 0.f, 0.f};

    const size_t s0 = (size_t)c * SC;
    const float* kbase = kk + (size_t)n * Sd * 512 + h * Dd;
    const float* vbase = vv + (size_t)n * Sd * 512 + h * Mm;
    const float* mbase = mask + (size_t)n * Sd;

    float4 kr[2], vr[2];
    float mr[2];

    #pragma unroll
    for (int p = 0; p < 2; p++) {
        size_t sg = s0 + p * 16 + lrow;
        kr[p] = *(const float4*)(kbase + sg * 512 + lcol * 4);
        vr[p] = *(const float4*)(vbase + sg * 512 + lcol * 4);
        mr[p] = __ldg(mbase + sg);
    }

    for (int it = 0; it < SC / 32; it++) {
        // transform + store current tile to smem (consumes kr/vr/mr)
        #pragma unroll
        for (int p = 0; p < 2; p++) {
            int row = p * 16 + lrow;
            float pk0 = phi(kr[p].x) * mr[p], pk1 = phi(kr[p].y) * mr[p];
            float pk2 = phi(kr[p].z) * mr[p], pk3 = phi(kr[p].w) * mr[p];
            ks4[0] += pk0; ks4[1] += pk1; ks4[2] += pk2; ks4[3] += pk3;
            uint4 ku; ku.x = to_tf32(pk0); ku.y = to_tf32(pk1);
                      ku.z = to_tf32(pk2); ku.w = to_tf32(pk3);
            uint4 vu; vu.x = to_tf32(vr[p].x); vu.y = to_tf32(vr[p].y);
                      vu.z = to_tf32(vr[p].z); vu.w = to_tf32(vr[p].w);
            *(uint4*)&Ks[row][lcol * 4] = ku;
            *(uint4*)&Vs[row][lcol * 4] = vu;
        }

        // prefetch next tile BEFORE the barrier (overlaps barrier + mma)
        if (it + 1 < SC / 32) {
            #pragma unroll
            for (int p = 0; p < 2; p++) {
                size_t sg = s0 + (it + 1) * 32 + p * 16 + lrow;
                kr[p] = *(const float4*)(kbase + sg * 512 + lcol * 4);
                vr[p] = *(const float4*)(vbase + sg * 512 + lcol * 4);
                mr[p] = __ldg(mbase + sg);
            }
        }
        __syncthreads();

        // this warp's 16 s-rows: two k8 slabs
        #pragma unroll
        for (int k8 = 0; k8 < 2; k8++) {
            int sA = sh + k8 * 8 + q4;
            uint32_t b0[4], b1[4];
            #pragma unroll
            for (int j = 0; j < 4; j++) {
                b0[j] = __float_as_uint(Vs[sA][m0 + 8 * j + r]);
                b1[j] = __float_as_uint(Vs[sA + 4][m0 + 8 * j + r]);
            }
            #pragma unroll
            for (int mg = 0; mg < 2; mg++) {
                int dg = d0 + mg * 16;
                uint32_t a0 = __float_as_uint(Ks[sA][dg + r]);
                uint32_t a1 = __float_as_uint(Ks[sA][dg + r + 8]);
                uint32_t a2 = __float_as_uint(Ks[sA + 4][dg + r]);
                uint32_t a3 = __float_as_uint(Ks[sA + 4][dg + r + 8]);
                #pragma unroll
                for (int j = 0; j < 4; j++)
                    mma_tf32(acc[mg][j], a0, a1, a2, a3, b0[j], b1[j]);
            }
        }
        __syncthreads();
    }

    // ksum partial (all warps)
    #pragma unroll
    for (int q = 0; q < 4; q++) atomicAdd(&ksum_s[lcol * 4 + q], ks4[q]);

    // upper s-half warps deposit acc
    if (warp >= 4) {
        #pragma unroll
        for (int mg = 0; mg < 2; mg++)
            #pragma unroll
            for (int j = 0; j < 4; j++)
                *(float4*)&Red[wq][lane][(mg * 4 + j) * 4] =
                    make_float4(acc[mg][j][0], acc[mg][j][1], acc[mg][j][2], acc[mg][j][3]);
    }
    __syncthreads();

    if (tid < 64) g_Ksp[(c * NH + nh) * Dd + tid] = ksum_s[tid];

    if (warp < 4) {
        float* kvp = g_KVp + ((size_t)c * NH + nh) * (Dd * Mm);
        #pragma unroll
        for (int mg = 0; mg < 2; mg++) {
            #pragma unroll
            for (int j = 0; j < 4; j++) {
                float4 o = *(const float4*)&Red[wq][lane][(mg * 4 + j) * 4];
                int m = m0 + 8 * j + 2 * q4;
                int dg = d0 + mg * 16;
                *(float2*)&kvp[(dg + r) * Mm + m] =
                    make_float2(acc[mg][j][0] + o.x, acc[mg][j][1] + o.y);
                *(float2*)&kvp[(dg + r + 8) * Mm + m] =
                    make_float2(acc[mg][j][2] + o.z, acc[mg][j][3] + o.w);
            }
        }
    }
}

// ─────────────── Reduce: CH partials → final KV (as tf32 bits) / Ksum ─────────────
#define KV4 (NH * Dd * Mm / 4)     // 65536 float4
#define KS4 (NH * Dd / 4)          // 1024 float4
__global__ __launch_bounds__(256) void la_red_kernel() {
    int i = blockIdx.x * 256 + threadIdx.x;
    if (i < KV4) {
        float4 s = make_float4(0.f, 0.f, 0.f, 0.f);
        #pragma unroll
        for (int c = 0; c < CH; c++) {
            float4 x = *(const float4*)(g_KVp + (size_t)c * (NH * Dd * Mm) + i * 4);
            s.x += x.x; s.y += x.y; s.z += x.z; s.w += x.w;
        }
        uint4 u; u.x = to_tf32(s.x); u.y = to_tf32(s.y);
                 u.z = to_tf32(s.z); u.w = to_tf32(s.w);
        *(uint4*)(g_KV + i * 4) = u;
    } else if (i < KV4 + KS4) {
        int i2 = i - KV4;
        float4 s = make_float4(0.f, 0.f, 0.f, 0.f);
        #pragma unroll
        for (int c = 0; c < CH; c++) {
            float4 x = *(const float4*)(g_Ksp + c * (NH * Dd) + i2 * 4);
            s.x += x.x; s.y += x.y; s.z += x.z; s.w += x.w;
        }
        *(float4*)(g_Ksum + i2 * 4) = s;
    }
}

// ───────────── Phase 2: persistent per (segment, h, n); KV loaded once ────────────
// (exact 84.4us version: single Qs buffer, prefetch after barrier, 2 barriers/tile)
__global__ __launch_bounds__(256) void la_out_kernel(const float* __restrict__ qq,
                                                     float* __restrict__ out) {
    const int seg = blockIdx.x, h = blockIdx.y, n = blockIdx.z;
    const int nh = n * Hh + h;
    const int tid = threadIdx.x;
    const int warp = tid >> 5, lane = tid & 31;
    const int r = lane >> 2, q4 = lane & 3;
    const int l0 = (warp >> 1) * 16, m0 = (warp & 1) * 32;
    const int lrow = tid >> 4, lcol = tid & 15;

    __shared__ float Qs[64][76];    // [l][d], tf32-rounded phiQ
    __shared__ float KVs[64][72];   // [d][m], tf32 bits (pre-converted)
    __shared__ float Zs[64];

    float4 ksum4 = *(const float4*)(g_Ksum + nh * Dd + lcol * 4);

    // KV tile once per CTA
    const float* kvb = g_KV + (size_t)nh * (Dd * Mm);
    #pragma unroll
    for (int p = 0; p < 4; p++) {
        int idx4 = tid + p * 256;
        float4 x = *(const float4*)(kvb + idx4 * 4);
        *(float4*)&KVs[idx4 >> 4][(idx4 & 15) * 4] = x;
    }

    const size_t lbase = (size_t)n * Ld + (size_t)seg * (Ld / TS);
    const float* qseg = qq + lbase * 512 + h * Dd;
    float* oseg = out + lbase * 512 + h * Mm;

    float4 qr[4];
    #pragma unroll
    for (int p = 0; p < 4; p++)
        qr[p] = *(const float4*)(qseg + (size_t)(p * 16 + lrow) * 512 + lcol * 4);

    const int NT = (Ld / TS) / 64;   // 8 tiles
    #pragma unroll 1
    for (int it = 0; it < NT; it++) {
        // transform + Z + store to smem
        #pragma unroll
        for (int p = 0; p < 4; p++) {
            int row = p * 16 + lrow;
            float p0 = phi(qr[p].x), p1 = phi(qr[p].y), p2 = phi(qr[p].z), p3 = phi(qr[p].w);
            float dot = p0 * ksum4.x + p1 * ksum4.y + p2 * ksum4.z + p3 * ksum4.w;
            dot += __shfl_xor_sync(0xffffffff, dot, 1);
            dot += __shfl_xor_sync(0xffffffff, dot, 2);
            dot += __shfl_xor_sync(0xffffffff, dot, 4);
            dot += __shfl_xor_sync(0xffffffff, dot, 8);
            if (lcol == 0) Zs[row] = 1.f / (dot + EPSV);
            uint4 qu; qu.x = to_tf32(p0); qu.y = to_tf32(p1);
                      qu.z = to_tf32(p2); qu.w = to_tf32(p3);
            *(uint4*)&Qs[row][lcol * 4] = qu;
        }
        __syncthreads();

        // prefetch next tile (overlaps mma)
        if (it + 1 < NT) {
            #pragma unroll
            for (int p = 0; p < 4; p++)
                qr[p] = *(const float4*)(qseg + (size_t)((it + 1) * 64 + p * 16 + lrow) * 512 + lcol * 4);
        }

        float acc[4][4] = {};
        #pragma unroll
        for (int k8 = 0; k8 < 8; k8++) {
            int dk = k8 * 8;
            uint32_t a0 = __float_as_uint(Qs[l0 + r][dk + q4]);
            uint32_t a1 = __float_as_uint(Qs[l0 + r + 8][dk + q4]);
            uint32_t a2 = __float_as_uint(Qs[l0 + r][dk + q4 + 4]);
            uint32_t a3 = __float_as_uint(Qs[l0 + r + 8][dk + q4 + 4]);
            #pragma unroll
            for (int j = 0; j < 4; j++) {
                uint32_t b0 = __float_as_uint(KVs[dk + q4][m0 + 8 * j + r]);
                uint32_t b1 = __float_as_uint(KVs[dk + q4 + 4][m0 + 8 * j + r]);
                mma_tf32(acc[j], a0, a1, a2, a3, b0, b1);
            }
        }

        float* ob = oseg + (size_t)it * 64 * 512;
        #pragma unroll
        for (int j = 0; j < 4; j++) {
            int m = m0 + 8 * j + 2 * q4;
            int l1 = l0 + r, l2 = l0 + r + 8;
            float z1 = Zs[l1], z2 = Zs[l2];
            *(float2*)&ob[(size_t)l1 * 512 + m] = make_float2(acc[j][0] * z1, acc[j][1] * z1);
            *(float2*)&ob[(size_t)l2 * 512 + m] = make_float2(acc[j][2] * z2, acc[j][3] * z2);
        }
        __syncthreads();
    }
}

extern "C" void kernel_launch(void* const* d_in, const int* in_sizes, int n_in,
                              void* d_out, int out_size) {
    const float* q    = (const float*)d_in[0];
    const float* k    = (const float*)d_in[1];
    const float* v    = (const float*)d_in[2];
    const float* mask = (const float*)d_in[3];
    float* out = (float*)d_out;

    la_kv_kernel<<<dim3(CH, Hh, Nb), 256>>>(k, v, mask);
    la_red_kernel<<<(KV4 + KS4 + 255) / 256, 256>>>();
    la_out_kernel<<<dim3(TS, Hh, Nb), 256>>>(q, out);
}

// round 9
// speedup vs baseline: 1.6829x; 1.6829x over previous
#include <cuda_runtime.h>
#include <cuda_bf16.h>
#include <cstdint>

// Fixed shapes
#define Nb 8
#define Ld 4096
#define Sd 4096
#define Hh 8
#define Dd 64
#define Mm 64
#define CH 16           // split-K chunks over S
#define SC (Sd / CH)    // 256 s-rows per chunk
#define TS 4            // phase-2 L segments: 256 CTAs, one wave
#define EPSV 1e-6f
#define NH (Nb * Hh)

// Scratch (allocation-free rule: __device__ globals)
__device__ float g_KVp[CH * NH * Dd * Mm];   // per-chunk partial KV (fp32)
__device__ float g_Ksp[CH * NH * Dd];        // per-chunk partial Ksum (fp32)
__device__ float g_KV[NH * Dd * Mm];         // reduced KV (tf32 bit patterns)
__device__ float g_Ksum[NH * Dd];            // reduced Ksum (fp32)

__device__ __forceinline__ float phi(float x) {
    return x > 0.f ? x + 1.f : __expf(x);    // elu(x)+1
}

__device__ __forceinline__ uint32_t to_tf32(float x) {
    uint32_t u;
    asm("cvt.rna.tf32.f32 %0, %1;" : "=r"(u) : "f"(x));
    return u;
}

__device__ __forceinline__ void mma_tf32(float* d,
                                         uint32_t a0, uint32_t a1, uint32_t a2, uint32_t a3,
                                         uint32_t b0, uint32_t b1) {
    asm volatile(
        "mma.sync.aligned.m16n8k8.row.col.f32.tf32.tf32.f32 "
        "{%0,%1,%2,%3}, {%4,%5,%6,%7}, {%8,%9}, {%0,%1,%2,%3};\n"
        : "+f"(d[0]), "+f"(d[1]), "+f"(d[2]), "+f"(d[3])
        : "r"(a0), "r"(a1), "r"(a2), "r"(a3), "r"(b0), "r"(b1));
}

__device__ __forceinline__ void cp16(uint32_t saddr, const void* gaddr) {
    asm volatile("cp.async.ca.shared.global [%0], [%1], 16;\n"
                 :: "r"(saddr), "l"(gaddr));
}

// ───────────────────────── Phase 1: per-chunk KV partials ─────────────────────────
// (exact best-measured 35.2us version: single buffer, prefetch after barrier)
__global__ __launch_bounds__(256) void la_kv_kernel(const float* __restrict__ kk,
                                                    const float* __restrict__ vv,
                                                    const float* __restrict__ mask) {
    const int c = blockIdx.x, h = blockIdx.y, n = blockIdx.z;
    const int nh = n * Hh + h;
    const int tid = threadIdx.x;
    const int warp = tid >> 5, lane = tid & 31;
    const int r = lane >> 2, q4 = lane & 3;
    const int d0 = (warp >> 1) * 16, m0 = (warp & 1) * 32;
    const int lrow = tid >> 4, lcol = tid & 15;

    __shared__ float Ks[32][72];
    __shared__ float Vs[32][72];
    __shared__ float ksum_s[64];

    if (tid < 64) ksum_s[tid] = 0.f;

    float acc[4][4] = {};
    float ks4[4] = {0.f, 0.f, 0.f, 0.f};

    const size_t s0 = (size_t)c * SC;
    const float* kbase = kk + (size_t)n * Sd * 512 + h * Dd;
    const float* vbase = vv + (size_t)n * Sd * 512 + h * Mm;
    const float* mbase = mask + (size_t)n * Sd;

    float4 kr[2], vr[2];
    float mr[2];

    #pragma unroll
    for (int p = 0; p < 2; p++) {
        size_t sg = s0 + p * 16 + lrow;
        kr[p] = *(const float4*)(kbase + sg * 512 + lcol * 4);
        vr[p] = *(const float4*)(vbase + sg * 512 + lcol * 4);
        mr[p] = __ldg(mbase + sg);
    }

    for (int it = 0; it < SC / 32; it++) {
        #pragma unroll
        for (int p = 0; p < 2; p++) {
            int row = p * 16 + lrow;
            float pk0 = phi(kr[p].x) * mr[p], pk1 = phi(kr[p].y) * mr[p];
            float pk2 = phi(kr[p].z) * mr[p], pk3 = phi(kr[p].w) * mr[p];
            ks4[0] += pk0; ks4[1] += pk1; ks4[2] += pk2; ks4[3] += pk3;
            uint4 ku; ku.x = to_tf32(pk0); ku.y = to_tf32(pk1);
                      ku.z = to_tf32(pk2); ku.w = to_tf32(pk3);
            uint4 vu; vu.x = to_tf32(vr[p].x); vu.y = to_tf32(vr[p].y);
                      vu.z = to_tf32(vr[p].z); vu.w = to_tf32(vr[p].w);
            *(uint4*)&Ks[row][lcol * 4] = ku;
            *(uint4*)&Vs[row][lcol * 4] = vu;
        }
        __syncthreads();

        if (it + 1 < SC / 32) {
            #pragma unroll
            for (int p = 0; p < 2; p++) {
                size_t sg = s0 + (it + 1) * 32 + p * 16 + lrow;
                kr[p] = *(const float4*)(kbase + sg * 512 + lcol * 4);
                vr[p] = *(const float4*)(vbase + sg * 512 + lcol * 4);
                mr[p] = __ldg(mbase + sg);
            }
        }

        #pragma unroll
        for (int k8 = 0; k8 < 4; k8++) {
            int sA = k8 * 8 + q4;
            uint32_t a0 = __float_as_uint(Ks[sA][d0 + r]);
            uint32_t a1 = __float_as_uint(Ks[sA][d0 + r + 8]);
            uint32_t a2 = __float_as_uint(Ks[sA + 4][d0 + r]);
            uint32_t a3 = __float_as_uint(Ks[sA + 4][d0 + r + 8]);
            #pragma unroll
            for (int j = 0; j < 4; j++) {
                uint32_t b0 = __float_as_uint(Vs[sA][m0 + 8 * j + r]);
                uint32_t b1 = __float_as_uint(Vs[sA + 4][m0 + 8 * j + r]);
                mma_tf32(acc[j], a0, a1, a2, a3, b0, b1);
            }
        }
        __syncthreads();
    }

    #pragma unroll
    for (int q = 0; q < 4; q++) atomicAdd(&ksum_s[lcol * 4 + q], ks4[q]);
    __syncthreads();
    if (tid < 64) g_Ksp[(c * NH + nh) * Dd + tid] = ksum_s[tid];

    float* kvp = g_KVp + ((size_t)c * NH + nh) * (Dd * Mm);
    #pragma unroll
    for (int j = 0; j < 4; j++) {
        int m = m0 + 8 * j + 2 * q4;
        *(float2*)&kvp[(d0 + r) * Mm + m]     = make_float2(acc[j][0], acc[j][1]);
        *(float2*)&kvp[(d0 + r + 8) * Mm + m] = make_float2(acc[j][2], acc[j][3]);
    }
}

// ─────────────── Reduce: CH partials → final KV (as tf32 bits) / Ksum ─────────────
#define KV4 (NH * Dd * Mm / 4)     // 65536 float4
#define KS4 (NH * Dd / 4)          // 1024 float4
__global__ __launch_bounds__(256) void la_red_kernel() {
    int i = blockIdx.x * 256 + threadIdx.x;
    if (i < KV4) {
        float4 s = make_float4(0.f, 0.f, 0.f, 0.f);
        #pragma unroll
        for (int c = 0; c < CH; c++) {
            float4 x = *(const float4*)(g_KVp + (size_t)c * (NH * Dd * Mm) + i * 4);
            s.x += x.x; s.y += x.y; s.z += x.z; s.w += x.w;
        }
        uint4 u; u.x = to_tf32(s.x); u.y = to_tf32(s.y);
                 u.z = to_tf32(s.z); u.w = to_tf32(s.w);
        *(uint4*)(g_KV + i * 4) = u;
    } else if (i < KV4 + KS4) {
        int i2 = i - KV4;
        float4 s = make_float4(0.f, 0.f, 0.f, 0.f);
        #pragma unroll
        for (int c = 0; c < CH; c++) {
            float4 x = *(const float4*)(g_Ksp + c * (NH * Dd) + i2 * 4);
            s.x += x.x; s.y += x.y; s.z += x.z; s.w += x.w;
        }
        *(float4*)(g_Ksum + i2 * 4) = s;
    }
}

// ───────────── Phase 2: warp-autonomous, cp.async 2-stage ring, no block barriers ──
// grid (TS, H, N) = 256 CTAs, 256 threads. Warp w handles 16-row tiles
// t = it*8 + w, it = 0..7 (1024 rows per CTA). Full m=0..63 per warp.
#define QROWP 68                       // raw-Q smem row pitch (floats)
#define SLOT  (16 * QROWP)             // one stage (floats)
#define P2_SMEM ((64 * 72 + 8 * 2 * SLOT) * 4)   // 88064 bytes

__global__ __launch_bounds__(256) void la_out_kernel(const float* __restrict__ qq,
                                                     float* __restrict__ out) {
    extern __shared__ float sm[];
    float* KVs = sm;                       // [64][72] tf32 bits
    float* Qring = sm + 64 * 72;           // 8 warps x 2 stages x SLOT (raw fp32)

    const int seg = blockIdx.x, h = blockIdx.y, n = blockIdx.z;
    const int nh = n * Hh + h;
    const int tid = threadIdx.x;
    const int warp = tid >> 5, lane = tid & 31;
    const int r = lane >> 2, q4 = lane & 3;

    // cooperative KV load (tf32 bits, straight copy)
    const float* kvb = g_KV + (size_t)nh * (Dd * Mm);
    #pragma unroll
    for (int p = 0; p < 4; p++) {
        int idx4 = tid + p * 256;
        float4 x = *(const float4*)(kvb + idx4 * 4);
        *(float4*)&KVs[(idx4 >> 4) * 72 + (idx4 & 15) * 4] = x;
    }

    const size_t lbase = (size_t)n * Ld + (size_t)seg * (Ld / TS);
    const float* qseg = qq + lbase * 512 + h * Dd;
    float* oseg = out + lbase * 512 + h * Mm;

    float* myring = Qring + warp * 2 * SLOT;
    const uint32_t ring_s = (uint32_t)__cvta_generic_to_shared(myring);
    const int crow = lane >> 1, ccol = (lane & 1) * 8;   // 2 lanes per row, 8 float4-chunks each? no:
    // chunk map: chunk = lane + 32*i (i=0..7), row = chunk>>4, c = chunk&15 (16B units)

    const int NT = (Ld / TS) / (8 * 16);   // 8 iterations per warp

    // prologue: issue tiles it=0,1 into stages 0,1
    #pragma unroll
    for (int pre = 0; pre < 2; pre++) {
        int trow = (pre * 8 + warp) * 16;
        uint32_t sbase = ring_s + pre * SLOT * 4;
        #pragma unroll
        for (int i = 0; i < 8; i++) {
            int chunk = lane + 32 * i;
            int row = chunk >> 4, c = chunk & 15;
            cp16(sbase + (row * QROWP + c * 4) * 4,
                 qseg + (size_t)(trow + row) * 512 + c * 4);
        }
        asm volatile("cp.async.commit_group;\n");
    }

    __syncthreads();   // KVs ready (single block barrier in the kernel)

    // Ksum fragment columns for this lane: cols q4+8k and q4+4+8k
    float ksA[8], ksB[8];
    const float* ksb = g_Ksum + nh * Dd;
    #pragma unroll
    for (int k8 = 0; k8 < 8; k8++) {
        ksA[k8] = __ldg(ksb + 8 * k8 + q4);
        ksB[k8] = __ldg(ksb + 8 * k8 + q4 + 4);
    }

    #pragma unroll 1
    for (int it = 0; it < NT; it++) {
        float* qs = myring + (it & 1) * SLOT;

        // wait for group 'it' (exactly one group committed per iteration)
        asm volatile("cp.async.wait_group 1;\n" ::: "memory");
        __syncwarp();

        // read raw A fragments (16 rows x cols q4::4 for this lane)
        float ar[8][4];
        #pragma unroll
        for (int k8 = 0; k8 < 8; k8++) {
            int dk = 8 * k8;
            ar[k8][0] = qs[r * QROWP + dk + q4];
            ar[k8][1] = qs[(r + 8) * QROWP + dk + q4];
            ar[k8][2] = qs[r * QROWP + dk + q4 + 4];
            ar[k8][3] = qs[(r + 8) * QROWP + dk + q4 + 4];
        }
        __syncwarp();   // all lanes done reading this stage

        // refill this stage with tile it+2 (always commit to keep group count fixed)
        if (it + 2 < NT) {
            int trow = ((it + 2) * 8 + warp) * 16;
            uint32_t sbase = ring_s + (it & 1) * SLOT * 4;
            #pragma unroll
            for (int i = 0; i < 8; i++) {
                int chunk = lane + 32 * i;
                int row = chunk >> 4, c = chunk & 15;
                cp16(sbase + (row * QROWP + c * 4) * 4,
                     qseg + (size_t)(trow + row) * 512 + c * 4);
            }
        }
        asm volatile("cp.async.commit_group;\n");

        // phi + Z partials + tf32 convert
        float d1 = 0.f, d2 = 0.f;
        uint32_t af[8][4];
        #pragma unroll
        for (int k8 = 0; k8 < 8; k8++) {
            float p0 = phi(ar[k8][0]), p1 = phi(ar[k8][1]);
            float p2 = phi(ar[k8][2]), p3 = phi(ar[k8][3]);
            d1 += p0 * ksA[k8] + p2 * ksB[k8];
            d2 += p1 * ksA[k8] + p3 * ksB[k8];
            af[k8][0] = to_tf32(p0); af[k8][1] = to_tf32(p1);
            af[k8][2] = to_tf32(p2); af[k8][3] = to_tf32(p3);
        }
        d1 += __shfl_xor_sync(0xffffffff, d1, 1);
        d1 += __shfl_xor_sync(0xffffffff, d1, 2);
        d2 += __shfl_xor_sync(0xffffffff, d2, 1);
        d2 += __shfl_xor_sync(0xffffffff, d2, 2);
        float z1 = 1.f / (d1 + EPSV);
        float z2 = 1.f / (d2 + EPSV);

        // mma: 16 x 64 output, acc[j] = 16x8 n-tile j
        float acc[8][4] = {};
        #pragma unroll
        for (int k8 = 0; k8 < 8; k8++) {
            int dk = 8 * k8;
            #pragma unroll
            for (int j = 0; j < 8; j++) {
                uint32_t b0 = __float_as_uint(KVs[(dk + q4) * 72 + 8 * j + r]);
                uint32_t b1 = __float_as_uint(KVs[(dk + q4 + 4) * 72 + 8 * j + r]);
                mma_tf32(acc[j], af[k8][0], af[k8][1], af[k8][2], af[k8][3], b0, b1);
            }
        }

        // store
        int trow = (it * 8 + warp) * 16;
        float* ob = oseg + (size_t)trow * 512;
        #pragma unroll
        for (int j = 0; j < 8; j++) {
            int m = 8 * j + 2 * q4;
            *(float2*)&ob[(size_t)r * 512 + m] =
                make_float2(acc[j][0] * z1, acc[j][1] * z1);
            *(float2*)&ob[(size_t)(r + 8) * 512 + m] =
                make_float2(acc[j][2] * z2, acc[j][3] * z2);
        }
    }
}

extern "C" void kernel_launch(void* const* d_in, const int* in_sizes, int n_in,
                              void* d_out, int out_size) {
    const float* q    = (const float*)d_in[0];
    const float* k    = (const float*)d_in[1];
    const float* v    = (const float*)d_in[2];
    const float* mask = (const float*)d_in[3];
    float* out = (float*)d_out;

    static bool attr_set = false;
    if (!attr_set) {
        cudaFuncSetAttribute(la_out_kernel,
                             cudaFuncAttributeMaxDynamicSharedMemorySize, P2_SMEM);
        attr_set = true;
    }

    la_kv_kernel<<<dim3(CH, Hh, Nb), 256>>>(k, v, mask);
    la_red_kernel<<<(KV4 + KS4 + 255) / 256, 256>>>();
    la_out_kernel<<<dim3(TS, Hh, Nb), 256, P2_SMEM>>>(q, out);
}